// round 7
// baseline (speedup 1.0000x reference)
#include <cuda_runtime.h>
#include <cuda_fp16.h>
#include <math.h>

#define BATCH   256
#define JN      10
#define ICAPS   1152
#define DN      16
#define JD      160          // JN*DN
#define BJD     (BATCH*JD)   // 40960
#define BT      32           // b per pass CTA
#define IT      16           // i per pass CTA
#define IB      4            // i batch (sync cadence)
#define NP      (ICAPS/IT)   // 72 partial slices

// -------- scratch ------------------------------------------------------
// u_hat layout: [j][i][b][16 x half]  (32B per (j,i,b) entry)
__device__ __align__(1024) __half g_uhat[(size_t)JN * ICAPS * BATCH * DN]; // ~94.4MB
__device__ float g_acc[2 * BJD];                 // [0]=s0raw, [1]=s1
__device__ float g_part[(size_t)NP * BJD];       // ~11.8 MB (reused 3x)

// -------- helpers -------------------------------------------------------
typedef unsigned long long u64t;
__device__ __forceinline__ u64t pack2(float x, float y) {
    u64t r; asm("mov.b64 %0, {%1, %2};" : "=l"(r) : "f"(x), "f"(y)); return r;
}
__device__ __forceinline__ void unpack2(u64t v, float& x, float& y) {
    asm("mov.b64 {%0, %1}, %2;" : "=f"(x), "=f"(y) : "l"(v));
}
__device__ __forceinline__ u64t fma2(u64t a, u64t b, u64t c) {
    u64t d; asm("fma.rn.f32x2 %0, %1, %2, %3;" : "=l"(d) : "l"(a), "l"(b), "l"(c));
    return d;
}
__device__ __forceinline__ u64t addf2(u64t a, u64t b) {
    u64t d; asm("add.rn.f32x2 %0, %1, %2;" : "=l"(d) : "l"(a), "l"(b)); return d;
}
// 256-bit load (sm_100+). volatile: prevent CSE so phase-B reload stays a load.
__device__ __forceinline__ void ldg256(const void* p, uint4& lo, uint4& hi) {
    asm volatile("ld.global.nc.v8.b32 {%0,%1,%2,%3,%4,%5,%6,%7}, [%8];"
        : "=r"(lo.x), "=r"(lo.y), "=r"(lo.z), "=r"(lo.w),
          "=r"(hi.x), "=r"(hi.y), "=r"(hi.z), "=r"(hi.w)
        : "l"(p));
}

// -------- K1: u_hat = W @ x (fp16, [j][i][b] layout) + s0 partial slice --
// grid (72, 8), 320 threads: t%80 = jd2 (j*8+dp), t/80 = seg (4 b-pairs each)
__global__ __launch_bounds__(320, 2) void k_uhat(const float* __restrict__ x,
                                                 const float* __restrict__ W) {
    __shared__ __align__(16) float xs[16 * 4 * 16 * 4];   // 16 KB interleaved x
    const int i0 = blockIdx.x * 16;
    const int b0 = blockIdx.y * 32;
    const int t  = threadIdx.x;

    const float4* xg = (const float4*)x;   // [256][1152][8] -> 2304 f4 per b
    for (int f = t; f < 1024; f += 320) {
        int b = f >> 5, q = f & 31;            // q = ii*2 + qe
        float4 v = xg[(size_t)(b0 + b) * 2304 + (size_t)i0 * 2 + q];
        int ii = q >> 1, qe = q & 1;
        int b2 = b >> 1, bl = b & 1;
        float* p = xs + ii * 256 + qe * 128 + b2 * 4 + bl;
        p[0] = v.x; p[2] = v.y; p[64] = v.z; p[66] = v.w;
    }
    __syncthreads();

    const int jd2 = t % 80;          // j*8 + dp  (d0 = 2*dp)
    const int seg = t / 80;
    const int j   = jd2 >> 3, dp = jd2 & 7;
    const float4* Wg = (const float4*)W + (size_t)j * 36864 + dp * 4;
    __half2* uh2 = (__half2*)g_uhat;
    const ulonglong2* xq2base = (const ulonglong2*)xs;

    const int b2base = seg * 4;
    u64t s0a[4] = {0,0,0,0};
    u64t s1a[4] = {0,0,0,0};
    for (int ii = 0; ii < 16; ii++) {
        const int i = i0 + ii;
        const float4 w00 = Wg[(size_t)i * 32];
        const float4 w01 = Wg[(size_t)i * 32 + 1];
        const float4 w10 = Wg[(size_t)i * 32 + 2];
        const float4 w11 = Wg[(size_t)i * 32 + 3];
        u64t wd0[8], wd1[8];
        wd0[0]=pack2(w00.x,w00.x); wd0[1]=pack2(w00.y,w00.y);
        wd0[2]=pack2(w00.z,w00.z); wd0[3]=pack2(w00.w,w00.w);
        wd0[4]=pack2(w01.x,w01.x); wd0[5]=pack2(w01.y,w01.y);
        wd0[6]=pack2(w01.z,w01.z); wd0[7]=pack2(w01.w,w01.w);
        wd1[0]=pack2(w10.x,w10.x); wd1[1]=pack2(w10.y,w10.y);
        wd1[2]=pack2(w10.z,w10.z); wd1[3]=pack2(w10.w,w10.w);
        wd1[4]=pack2(w11.x,w11.x); wd1[5]=pack2(w11.y,w11.y);
        wd1[6]=pack2(w11.z,w11.z); wd1[7]=pack2(w11.w,w11.w);
        const ulonglong2* xq2 = xq2base + ii * 64;
        const size_t obase = ((size_t)j * ICAPS + i) * BATCH;
        #pragma unroll
        for (int bp = 0; bp < 4; bp++) {
            const int b2 = b2base + bp;
            u64t a0 = 0, a1 = 0;
            #pragma unroll
            for (int e2 = 0; e2 < 4; e2++) {
                ulonglong2 xv = xq2[e2 * 16 + b2];
                a0 = fma2(wd0[2*e2],   xv.x, a0);
                a0 = fma2(wd0[2*e2+1], xv.y, a0);
                a1 = fma2(wd1[2*e2],   xv.x, a1);
                a1 = fma2(wd1[2*e2+1], xv.y, a1);
            }
            float u00,u01,u10,u11;
            unpack2(a0, u00, u01);   // d0   : b_even, b_odd
            unpack2(a1, u10, u11);   // d0+1 : b_even, b_odd
            const int bg = b0 + 2*b2;
            uh2[(obase + bg)     * 8 + dp] = __floats2half2_rn(u00, u10);
            uh2[(obase + bg + 1) * 8 + dp] = __floats2half2_rn(u01, u11);
            s0a[bp] = addf2(s0a[bp], a0);
            s1a[bp] = addf2(s1a[bp], a1);
        }
    }
    // ---- s0 partial slice (no atomics): slice = blockIdx.x ----
    float* base = g_part + (size_t)blockIdx.x * BJD;
    #pragma unroll
    for (int bp = 0; bp < 4; bp++) {
        float p0,p1,q0,q1;
        unpack2(s0a[bp], p0, p1);
        unpack2(s1a[bp], q0, q1);
        const int bg = b0 + 2*(b2base + bp);
        *(float2*)(base + (size_t)bg * JD + jd2*2)       = make_float2(p0, q0);
        *(float2*)(base + (size_t)(bg+1) * JD + jd2*2)   = make_float2(p1, q1);
    }
}

// -------- k_reduce: g_acc[slot] = sum of NP partial slices ---------------
__global__ void k_reduce(int slot) {
    const int idx = blockIdx.x * 256 + threadIdx.x;   // < BJD
    float s = 0.f;
    #pragma unroll 8
    for (int p = 0; p < NP; p++) s += g_part[(size_t)p * BJD + idx];
    g_acc[slot * BJD + idx] = s;
}

// -------- k_pass: register-resident routing pass -------------------------
// grid (72, 8), block (32 b, 10 j). round = 1 or 2. Partials -> g_part.
__global__ __launch_bounds__(320, 3) void k_pass(int round) {
    __shared__ float se[2][IB][JN][BT];   // e-values, 10 KB

    const int lane = threadIdx.x;          // b within tile
    const int j    = threadIdx.y;
    const int b    = blockIdx.y * BT + lane;
    const int i0   = blockIdx.x * IT;

    // ---- vs[j,:] = v0 (+ v1) in registers ----
    float vs[DN];
    {
        float tmp[DN]; float sq = 0.f;
        const float* a0 = g_acc + b * JD + j * DN;
        #pragma unroll
        for (int d = 0; d < DN; d++) { tmp[d] = 0.1f * a0[d]; sq += tmp[d]*tmp[d]; }
        float sc = (sq / (1.0f + sq)) * rsqrtf(sq + 1e-7f);
        #pragma unroll
        for (int d = 0; d < DN; d++) vs[d] = tmp[d] * sc;
        if (round == 2) {
            const float* a1 = g_acc + BJD + b * JD + j * DN;
            sq = 0.f;
            #pragma unroll
            for (int d = 0; d < DN; d++) { tmp[d] = a1[d]; sq += tmp[d]*tmp[d]; }
            sc = (sq / (1.0f + sq)) * rsqrtf(sq + 1e-7f);
            #pragma unroll
            for (int d = 0; d < DN; d++) vs[d] += tmp[d] * sc;
        }
    }

    const char* up0 = (const char*)g_uhat
                    + (((size_t)j * ICAPS + i0) * BATCH + b) * 32;

    float s[DN];
    #pragma unroll
    for (int d = 0; d < DN; d++) s[d] = 0.f;

    int buf = 0;
    for (int t0 = 0; t0 < IT; t0 += IB) {
        // ---- phase A: 256-bit load, dot, exp, publish e ----
        float ev[IB];
        #pragma unroll
        for (int k = 0; k < IB; k++) {
            uint4 lo, hi;
            ldg256(up0 + (size_t)(t0 + k) * (BATCH * 32), lo, hi);
            const __half2* h0 = (const __half2*)&lo;
            const __half2* h1 = (const __half2*)&hi;
            float a = 0.f;
            #pragma unroll
            for (int d2 = 0; d2 < 4; d2++) {
                float2 f0 = __half22float2(h0[d2]);
                a = fmaf(f0.x, vs[2*d2],     a);
                a = fmaf(f0.y, vs[2*d2 + 1], a);
                float2 f1 = __half22float2(h1[d2]);
                a = fmaf(f1.x, vs[8 + 2*d2], a);
                a = fmaf(f1.y, vs[9 + 2*d2], a);
            }
            ev[k] = __expf(a);
            se[buf][k][j][lane] = ev[k];
        }
        __syncthreads();
        // ---- phase B: normalize + accumulate (reload = L1 hit) ----
        #pragma unroll
        for (int k = 0; k < IB; k++) {
            float sum = 0.f;
            #pragma unroll
            for (int jj = 0; jj < JN; jj++) sum += se[buf][k][jj][lane];
            float c = __fdividef(ev[k], sum);
            uint4 lo, hi;
            ldg256(up0 + (size_t)(t0 + k) * (BATCH * 32), lo, hi);
            const __half2* h0 = (const __half2*)&lo;
            const __half2* h1 = (const __half2*)&hi;
            #pragma unroll
            for (int d2 = 0; d2 < 4; d2++) {
                float2 f0 = __half22float2(h0[d2]);
                s[2*d2]     = fmaf(f0.x, c, s[2*d2]);
                s[2*d2 + 1] = fmaf(f0.y, c, s[2*d2 + 1]);
                float2 f1 = __half22float2(h1[d2]);
                s[8 + 2*d2] = fmaf(f1.x, c, s[8 + 2*d2]);
                s[9 + 2*d2] = fmaf(f1.y, c, s[9 + 2*d2]);
            }
        }
        buf ^= 1;
    }

    // ---- write per-CTA partial (coalesced float4 stores) ----
    float* dst = g_part + (size_t)blockIdx.x * BJD + (size_t)b * JD + j * DN;
    #pragma unroll
    for (int q = 0; q < 4; q++)
        ((float4*)dst)[q] = make_float4(s[4*q], s[4*q+1], s[4*q+2], s[4*q+3]);
}

// -------- k_final: out = squash(sum of partials) -------------------------
__global__ __launch_bounds__(1024) void k_final(float* __restrict__ out) {
    const int idx = blockIdx.x * 1024 + threadIdx.x;   // b*160 + jd
    float v = 0.f;
    #pragma unroll 8
    for (int p = 0; p < NP; p++) v += g_part[(size_t)p * BJD + idx];
    float sq = v * v;
    sq += __shfl_xor_sync(0xffffffff, sq, 1);
    sq += __shfl_xor_sync(0xffffffff, sq, 2);
    sq += __shfl_xor_sync(0xffffffff, sq, 4);
    sq += __shfl_xor_sync(0xffffffff, sq, 8);
    float sc = (sq / (1.0f + sq)) * rsqrtf(sq + 1e-7f);
    out[idx] = v * sc;
}

// -------- launch --------------------------------------------------------
extern "C" void kernel_launch(void* const* d_in, const int* in_sizes, int n_in,
                              void* d_out, int out_size) {
    const float* x = (const float*)d_in[0];   // [256,1152,8]
    const float* W = (const float*)d_in[1];   // [10,1152,16,8]
    float* out = (float*)d_out;               // [256,10,16]

    k_uhat<<<dim3(ICAPS / 16, BATCH / 32), 320>>>(x, W);
    k_reduce<<<BJD / 256, 256>>>(0);                       // s0
    k_pass<<<dim3(NP, BATCH / BT), dim3(BT, JN)>>>(1);
    k_reduce<<<BJD / 256, 256>>>(1);                       // s1
    k_pass<<<dim3(NP, BATCH / BT), dim3(BT, JN)>>>(2);
    k_final<<<BJD / 1024, 1024>>>(out);
}

// round 8
// speedup vs baseline: 1.1864x; 1.1864x over previous
#include <cuda_runtime.h>
#include <cuda_fp16.h>
#include <math.h>

#define BATCH   256
#define JN      10
#define ICAPS   1152
#define DN      16
#define JD      160          // JN*DN
#define BJD     (BATCH*JD)   // 40960
#define BT      16           // b per pass CTA
#define IT      32           // i per pass CTA
#define IB      4            // i batch (sync cadence)
#define NP      (ICAPS/IT)   // 36 partial slices

// -------- scratch ------------------------------------------------------
// u_hat SoA: plane 0 = d0..7, plane 1 = d8..15; 16B per (j,i,b) per plane
#define PLANEH  ((size_t)JN * ICAPS * BATCH * 8)    // halves per plane
__device__ __align__(1024) __half g_uhat[2 * PLANEH];   // ~94.4 MB
__device__ float g_acc[2 * BJD];                 // [0]=s0raw, [1]=s1
__device__ float g_part[(size_t)NP * BJD];       // ~5.9 MB

// -------- f32x2 helpers (k_uhat) ----------------------------------------
typedef unsigned long long u64t;
__device__ __forceinline__ u64t pack2(float x, float y) {
    u64t r; asm("mov.b64 %0, {%1, %2};" : "=l"(r) : "f"(x), "f"(y)); return r;
}
__device__ __forceinline__ void unpack2(u64t v, float& x, float& y) {
    asm("mov.b64 {%0, %1}, %2;" : "=f"(x), "=f"(y) : "l"(v));
}
__device__ __forceinline__ u64t fma2(u64t a, u64t b, u64t c) {
    u64t d; asm("fma.rn.f32x2 %0, %1, %2, %3;" : "=l"(d) : "l"(a), "l"(b), "l"(c));
    return d;
}
__device__ __forceinline__ u64t addf2(u64t a, u64t b) {
    u64t d; asm("add.rn.f32x2 %0, %1, %2;" : "=l"(d) : "l"(a), "l"(b)); return d;
}

// -------- K1: u_hat = W @ x (fp16, SoA planes), fused partial s0 ---------
// grid (72, 4), 320 threads: t%80 = jd2 (j*8+dp), t/80 = seg (16 b each)
__global__ __launch_bounds__(320, 2) void k_uhat(const float* __restrict__ x,
                                                 const float* __restrict__ W) {
    __shared__ __align__(16) float xs[16 * 4 * 32 * 4];   // 32 KB interleaved x
    const int i0 = blockIdx.x * 16;
    const int b0 = blockIdx.y * 64;
    const int t  = threadIdx.x;

    const float4* xg = (const float4*)x;   // [256][1152][8] -> 2304 f4 per b
    for (int f = t; f < 2048; f += 320) {
        int b = f >> 5, q = f & 31;            // q = ii*2 + qe
        float4 v = xg[(size_t)(b0 + b) * 2304 + (size_t)i0 * 2 + q];
        int ii = q >> 1, qe = q & 1;
        int b2 = b >> 1, bl = b & 1;
        float* p = xs + (ii * 128 + qe * 64 + b2) * 4 + bl;
        p[0] = v.x; p[2] = v.y; p[128] = v.z; p[130] = v.w;
    }
    __syncthreads();

    const int jd2 = t % 80;          // j*8 + dp  (d0 = 2*dp)
    const int seg = t / 80;
    const int j   = jd2 >> 3, dp = jd2 & 7;
    const int pl  = dp >> 2, dq = dp & 3;      // SoA plane / in-plane pair
    const float4* Wg = (const float4*)W + (size_t)j * 36864 + dp * 4;
    __half2* uh2 = (__half2*)g_uhat + (size_t)pl * (PLANEH / 2) + dq;
    const ulonglong2* xq2base = (const ulonglong2*)xs;

    for (int bt = 0; bt < 2; bt++) {
        const int b2base = seg * 8 + bt * 4;
        u64t s0a[4] = {0,0,0,0};
        u64t s1a[4] = {0,0,0,0};
        for (int ii = 0; ii < 16; ii++) {
            const int i = i0 + ii;
            const float4 w00 = Wg[(size_t)i * 32];
            const float4 w01 = Wg[(size_t)i * 32 + 1];
            const float4 w10 = Wg[(size_t)i * 32 + 2];
            const float4 w11 = Wg[(size_t)i * 32 + 3];
            u64t wd0[8], wd1[8];
            wd0[0]=pack2(w00.x,w00.x); wd0[1]=pack2(w00.y,w00.y);
            wd0[2]=pack2(w00.z,w00.z); wd0[3]=pack2(w00.w,w00.w);
            wd0[4]=pack2(w01.x,w01.x); wd0[5]=pack2(w01.y,w01.y);
            wd0[6]=pack2(w01.z,w01.z); wd0[7]=pack2(w01.w,w01.w);
            wd1[0]=pack2(w10.x,w10.x); wd1[1]=pack2(w10.y,w10.y);
            wd1[2]=pack2(w10.z,w10.z); wd1[3]=pack2(w10.w,w10.w);
            wd1[4]=pack2(w11.x,w11.x); wd1[5]=pack2(w11.y,w11.y);
            wd1[6]=pack2(w11.z,w11.z); wd1[7]=pack2(w11.w,w11.w);
            const ulonglong2* xq2 = xq2base + ii * 128;
            const size_t obase = ((size_t)j * ICAPS + i) * BATCH;
            #pragma unroll
            for (int bp = 0; bp < 4; bp++) {
                const int b2 = b2base + bp;
                u64t a0 = 0, a1 = 0;
                #pragma unroll
                for (int e2 = 0; e2 < 4; e2++) {
                    ulonglong2 xv = xq2[e2 * 32 + b2];
                    a0 = fma2(wd0[2*e2],   xv.x, a0);
                    a0 = fma2(wd0[2*e2+1], xv.y, a0);
                    a1 = fma2(wd1[2*e2],   xv.x, a1);
                    a1 = fma2(wd1[2*e2+1], xv.y, a1);
                }
                float u00,u01,u10,u11;
                unpack2(a0, u00, u01);   // d0   : b_even, b_odd
                unpack2(a1, u10, u11);   // d0+1 : b_even, b_odd
                const int bg = b0 + 2*b2;
                uh2[(obase + bg)     * 4] = __floats2half2_rn(u00, u10);
                uh2[(obase + bg + 1) * 4] = __floats2half2_rn(u01, u11);
                s0a[bp] = addf2(s0a[bp], a0);
                s1a[bp] = addf2(s1a[bp], a1);
            }
        }
        #pragma unroll
        for (int bp = 0; bp < 4; bp++) {
            float p0,p1,q0,q1;
            unpack2(s0a[bp], p0, p1);
            unpack2(s1a[bp], q0, q1);
            float* sb = &g_acc[(b0 + 2*(b2base+bp)) * JD + jd2 * 2];
            atomicAdd(sb,           p0);
            atomicAdd(sb + 1,       q0);
            atomicAdd(sb + JD,      p1);
            atomicAdd(sb + JD + 1,  q1);
        }
    }
}

// -------- k_pass: register-resident routing pass -------------------------
// grid (36, 16), block (16 b, 10 j). round = 1 or 2. Partials -> g_part.
__global__ __launch_bounds__(160, 6) void k_pass(int round) {
    __shared__ float se[2][IB][JN][BT];   // e-values, 5 KB

    const int lane = threadIdx.x;          // b within tile
    const int j    = threadIdx.y;
    const int b    = blockIdx.y * BT + lane;
    const int i0   = blockIdx.x * IT;

    // ---- vs[j,:] = v0 (+ v1) in registers ----
    float vs[DN];
    {
        float tmp[DN]; float sq = 0.f;
        const float* a0 = g_acc + b * JD + j * DN;
        #pragma unroll
        for (int d = 0; d < DN; d++) { tmp[d] = 0.1f * a0[d]; sq += tmp[d]*tmp[d]; }
        float sc = (sq / (1.0f + sq)) * rsqrtf(sq + 1e-7f);
        #pragma unroll
        for (int d = 0; d < DN; d++) vs[d] = tmp[d] * sc;
        if (round == 2) {
            const float* a1 = g_acc + BJD + b * JD + j * DN;
            sq = 0.f;
            #pragma unroll
            for (int d = 0; d < DN; d++) { tmp[d] = a1[d]; sq += tmp[d]*tmp[d]; }
            sc = (sq / (1.0f + sq)) * rsqrtf(sq + 1e-7f);
            #pragma unroll
            for (int d = 0; d < DN; d++) vs[d] += tmp[d] * sc;
        }
    }

    const uint4* u0 = (const uint4*)g_uhat;           // plane 0 (d0..7)
    const uint4* u1 = u0 + (PLANEH / 8);              // plane 1 (d8..15)
    const size_t e0 = ((size_t)j * ICAPS + i0) * BATCH + b;

    float s[DN];
    #pragma unroll
    for (int d = 0; d < DN; d++) s[d] = 0.f;

    int buf = 0;
    for (int t0 = 0; t0 < IT; t0 += IB) {
        // ---- phase A: dense 16B loads from both planes, dot, exp ----
        float ev[IB];
        #pragma unroll
        for (int k = 0; k < IB; k++) {
            const size_t ix = e0 + (size_t)(t0 + k) * BATCH;
            uint4 lo = __ldg(u0 + ix);
            uint4 hi = __ldg(u1 + ix);
            const __half2* h0 = (const __half2*)&lo;
            const __half2* h1 = (const __half2*)&hi;
            float a = 0.f;
            #pragma unroll
            for (int d2 = 0; d2 < 4; d2++) {
                float2 f0 = __half22float2(h0[d2]);
                a = fmaf(f0.x, vs[2*d2],     a);
                a = fmaf(f0.y, vs[2*d2 + 1], a);
                float2 f1 = __half22float2(h1[d2]);
                a = fmaf(f1.x, vs[8 + 2*d2], a);
                a = fmaf(f1.y, vs[9 + 2*d2], a);
            }
            ev[k] = __expf(a);
            se[buf][k][j][lane] = ev[k];
        }
        __syncthreads();
        // ---- phase B: normalize + accumulate (reload = L1 hit) ----
        #pragma unroll
        for (int k = 0; k < IB; k++) {
            float sum = 0.f;
            #pragma unroll
            for (int jj = 0; jj < JN; jj++) sum += se[buf][k][jj][lane];
            float c = __fdividef(ev[k], sum);
            const size_t ix = e0 + (size_t)(t0 + k) * BATCH;
            uint4 lo = __ldg(u0 + ix);
            uint4 hi = __ldg(u1 + ix);
            const __half2* h0 = (const __half2*)&lo;
            const __half2* h1 = (const __half2*)&hi;
            #pragma unroll
            for (int d2 = 0; d2 < 4; d2++) {
                float2 f0 = __half22float2(h0[d2]);
                s[2*d2]     = fmaf(f0.x, c, s[2*d2]);
                s[2*d2 + 1] = fmaf(f0.y, c, s[2*d2 + 1]);
                float2 f1 = __half22float2(h1[d2]);
                s[8 + 2*d2] = fmaf(f1.x, c, s[8 + 2*d2]);
                s[9 + 2*d2] = fmaf(f1.y, c, s[9 + 2*d2]);
            }
        }
        buf ^= 1;
    }

    // ---- write per-CTA partial (coalesced float4 stores) ----
    float* dst = g_part + (size_t)blockIdx.x * BJD + (size_t)b * JD + j * DN;
    #pragma unroll
    for (int q = 0; q < 4; q++)
        ((float4*)dst)[q] = make_float4(s[4*q], s[4*q+1], s[4*q+2], s[4*q+3]);
}

// -------- k_reduce: s1 = sum of partials --------------------------------
__global__ void k_reduce() {
    const int idx = blockIdx.x * 256 + threadIdx.x;   // < BJD
    float s = 0.f;
    #pragma unroll 4
    for (int p = 0; p < NP; p++) s += g_part[(size_t)p * BJD + idx];
    g_acc[BJD + idx] = s;
}

// -------- k_final: out = squash(sum of partials) -------------------------
__global__ __launch_bounds__(1024) void k_final(float* __restrict__ out) {
    const int idx = blockIdx.x * 1024 + threadIdx.x;   // b*160 + jd
    float v = 0.f;
    #pragma unroll 4
    for (int p = 0; p < NP; p++) v += g_part[(size_t)p * BJD + idx];
    float sq = v * v;
    sq += __shfl_xor_sync(0xffffffff, sq, 1);
    sq += __shfl_xor_sync(0xffffffff, sq, 2);
    sq += __shfl_xor_sync(0xffffffff, sq, 4);
    sq += __shfl_xor_sync(0xffffffff, sq, 8);
    float sc = (sq / (1.0f + sq)) * rsqrtf(sq + 1e-7f);
    out[idx] = v * sc;
}

// -------- launch --------------------------------------------------------
extern "C" void kernel_launch(void* const* d_in, const int* in_sizes, int n_in,
                              void* d_out, int out_size) {
    const float* x = (const float*)d_in[0];   // [256,1152,8]
    const float* W = (const float*)d_in[1];   // [10,1152,16,8]
    float* out = (float*)d_out;               // [256,10,16]

    void* acc_ptr = nullptr;
    cudaGetSymbolAddress(&acc_ptr, g_acc);
    cudaMemsetAsync(acc_ptr, 0, BJD * sizeof(float));   // s0 only

    k_uhat<<<dim3(ICAPS / 16, BATCH / 64), 320>>>(x, W);
    k_pass<<<dim3(NP, BATCH / BT), dim3(BT, JN)>>>(1);
    k_reduce<<<BJD / 256, 256>>>();
    k_pass<<<dim3(NP, BATCH / BT), dim3(BT, JN)>>>(2);
    k_final<<<BJD / 1024, 1024>>>(out);
}

// round 9
// speedup vs baseline: 1.3932x; 1.1744x over previous
#include <cuda_runtime.h>
#include <cuda_fp16.h>
#include <math.h>

#define BATCH   256
#define JN      10
#define ICAPS   1152
#define DN      16
#define JD      160          // JN*DN
#define BJD     (BATCH*JD)   // 40960
#define BT      32           // b per pass CTA
#define IT      32           // i per pass CTA
#define IB      2            // i batch (register-resident)
#define NP      (ICAPS/IT)   // 36 partial slices

// -------- scratch ------------------------------------------------------
// u_hat SoA: plane 0 = d0..7, plane 1 = d8..15; 16B per (j,i,b) per plane
#define PLANEH  ((size_t)JN * ICAPS * BATCH * 8)    // halves per plane
__device__ __align__(1024) __half g_uhat[2 * PLANEH];   // ~94.4 MB
__device__ float g_acc[2 * BJD];                 // [0]=s0raw, [1]=s1
__device__ float g_part[(size_t)NP * BJD];       // ~5.9 MB

// -------- f32x2 helpers (k_uhat) ----------------------------------------
typedef unsigned long long u64t;
__device__ __forceinline__ u64t pack2(float x, float y) {
    u64t r; asm("mov.b64 %0, {%1, %2};" : "=l"(r) : "f"(x), "f"(y)); return r;
}
__device__ __forceinline__ void unpack2(u64t v, float& x, float& y) {
    asm("mov.b64 {%0, %1}, %2;" : "=f"(x), "=f"(y) : "l"(v));
}
__device__ __forceinline__ u64t fma2(u64t a, u64t b, u64t c) {
    u64t d; asm("fma.rn.f32x2 %0, %1, %2, %3;" : "=l"(d) : "l"(a), "l"(b), "l"(c));
    return d;
}
__device__ __forceinline__ u64t addf2(u64t a, u64t b) {
    u64t d; asm("add.rn.f32x2 %0, %1, %2;" : "=l"(d) : "l"(a), "l"(b)); return d;
}

// -------- K1: u_hat = W @ x (fp16, SoA planes), fused partial s0 ---------
// grid (72, 4), 320 threads: t%80 = jd2 (j*8+dp), t/80 = seg (16 b each)
__global__ __launch_bounds__(320, 2) void k_uhat(const float* __restrict__ x,
                                                 const float* __restrict__ W) {
    __shared__ __align__(16) float xs[16 * 4 * 32 * 4];   // 32 KB interleaved x
    const int i0 = blockIdx.x * 16;
    const int b0 = blockIdx.y * 64;
    const int t  = threadIdx.x;

    const float4* xg = (const float4*)x;   // [256][1152][8] -> 2304 f4 per b
    for (int f = t; f < 2048; f += 320) {
        int b = f >> 5, q = f & 31;            // q = ii*2 + qe
        float4 v = xg[(size_t)(b0 + b) * 2304 + (size_t)i0 * 2 + q];
        int ii = q >> 1, qe = q & 1;
        int b2 = b >> 1, bl = b & 1;
        float* p = xs + (ii * 128 + qe * 64 + b2) * 4 + bl;
        p[0] = v.x; p[2] = v.y; p[128] = v.z; p[130] = v.w;
    }
    __syncthreads();

    const int jd2 = t % 80;          // j*8 + dp  (d0 = 2*dp)
    const int seg = t / 80;
    const int j   = jd2 >> 3, dp = jd2 & 7;
    const int pl  = dp >> 2, dq = dp & 3;      // SoA plane / in-plane pair
    const float4* Wg = (const float4*)W + (size_t)j * 36864 + dp * 4;
    __half2* uh2 = (__half2*)g_uhat + (size_t)pl * (PLANEH / 2) + dq;
    const ulonglong2* xq2base = (const ulonglong2*)xs;

    for (int bt = 0; bt < 2; bt++) {
        const int b2base = seg * 8 + bt * 4;
        u64t s0a[4] = {0,0,0,0};
        u64t s1a[4] = {0,0,0,0};
        for (int ii = 0; ii < 16; ii++) {
            const int i = i0 + ii;
            const float4 w00 = Wg[(size_t)i * 32];
            const float4 w01 = Wg[(size_t)i * 32 + 1];
            const float4 w10 = Wg[(size_t)i * 32 + 2];
            const float4 w11 = Wg[(size_t)i * 32 + 3];
            u64t wd0[8], wd1[8];
            wd0[0]=pack2(w00.x,w00.x); wd0[1]=pack2(w00.y,w00.y);
            wd0[2]=pack2(w00.z,w00.z); wd0[3]=pack2(w00.w,w00.w);
            wd0[4]=pack2(w01.x,w01.x); wd0[5]=pack2(w01.y,w01.y);
            wd0[6]=pack2(w01.z,w01.z); wd0[7]=pack2(w01.w,w01.w);
            wd1[0]=pack2(w10.x,w10.x); wd1[1]=pack2(w10.y,w10.y);
            wd1[2]=pack2(w10.z,w10.z); wd1[3]=pack2(w10.w,w10.w);
            wd1[4]=pack2(w11.x,w11.x); wd1[5]=pack2(w11.y,w11.y);
            wd1[6]=pack2(w11.z,w11.z); wd1[7]=pack2(w11.w,w11.w);
            const ulonglong2* xq2 = xq2base + ii * 128;
            const size_t obase = ((size_t)j * ICAPS + i) * BATCH;
            #pragma unroll
            for (int bp = 0; bp < 4; bp++) {
                const int b2 = b2base + bp;
                u64t a0 = 0, a1 = 0;
                #pragma unroll
                for (int e2 = 0; e2 < 4; e2++) {
                    ulonglong2 xv = xq2[e2 * 32 + b2];
                    a0 = fma2(wd0[2*e2],   xv.x, a0);
                    a0 = fma2(wd0[2*e2+1], xv.y, a0);
                    a1 = fma2(wd1[2*e2],   xv.x, a1);
                    a1 = fma2(wd1[2*e2+1], xv.y, a1);
                }
                float u00,u01,u10,u11;
                unpack2(a0, u00, u01);   // d0   : b_even, b_odd
                unpack2(a1, u10, u11);   // d0+1 : b_even, b_odd
                const int bg = b0 + 2*b2;
                uh2[(obase + bg)     * 4] = __floats2half2_rn(u00, u10);
                uh2[(obase + bg + 1) * 4] = __floats2half2_rn(u01, u11);
                s0a[bp] = addf2(s0a[bp], a0);
                s1a[bp] = addf2(s1a[bp], a1);
            }
        }
        #pragma unroll
        for (int bp = 0; bp < 4; bp++) {
            float p0,p1,q0,q1;
            unpack2(s0a[bp], p0, p1);
            unpack2(s1a[bp], q0, q1);
            float* sb = &g_acc[(b0 + 2*(b2base+bp)) * JD + jd2 * 2];
            atomicAdd(sb,           p0);
            atomicAdd(sb + 1,       q0);
            atomicAdd(sb + JD,      p1);
            atomicAdd(sb + JD + 1,  q1);
        }
    }
}

// -------- k_pass: register-resident routing pass -------------------------
// grid (36, 8), block (32 b, 10 j). round = 1 or 2. Partials -> g_part.
__global__ __launch_bounds__(320, 3) void k_pass(int round) {
    __shared__ float se[2][IB][JN][BT];   // e-values, 5 KB

    const int lane = threadIdx.x;          // b within tile
    const int j    = threadIdx.y;
    const int b    = blockIdx.y * BT + lane;
    const int i0   = blockIdx.x * IT;

    // ---- vs[j,:] = v0 (+ v1) in registers ----
    float vs[DN];
    {
        float tmp[DN]; float sq = 0.f;
        const float* a0 = g_acc + b * JD + j * DN;
        #pragma unroll
        for (int d = 0; d < DN; d++) { tmp[d] = 0.1f * a0[d]; sq += tmp[d]*tmp[d]; }
        float sc = (sq / (1.0f + sq)) * rsqrtf(sq + 1e-7f);
        #pragma unroll
        for (int d = 0; d < DN; d++) vs[d] = tmp[d] * sc;
        if (round == 2) {
            const float* a1 = g_acc + BJD + b * JD + j * DN;
            sq = 0.f;
            #pragma unroll
            for (int d = 0; d < DN; d++) { tmp[d] = a1[d]; sq += tmp[d]*tmp[d]; }
            sc = (sq / (1.0f + sq)) * rsqrtf(sq + 1e-7f);
            #pragma unroll
            for (int d = 0; d < DN; d++) vs[d] += tmp[d] * sc;
        }
    }

    const uint4* u0 = (const uint4*)g_uhat;           // plane 0 (d0..7)
    const uint4* u1 = u0 + (PLANEH / 8);              // plane 1 (d8..15)
    const size_t e0 = ((size_t)j * ICAPS + i0) * BATCH + b;

    float s[DN];
    #pragma unroll
    for (int d = 0; d < DN; d++) s[d] = 0.f;

    int buf = 0;
    for (int t0 = 0; t0 < IT; t0 += IB) {
        // ---- phase A: dense 16B loads (held in regs), dot, exp ----
        float ev[IB];
        uint4 lo[IB], hi[IB];
        #pragma unroll
        for (int k = 0; k < IB; k++) {
            const size_t ix = e0 + (size_t)(t0 + k) * BATCH;
            lo[k] = __ldg(u0 + ix);
            hi[k] = __ldg(u1 + ix);
            const __half2* h0 = (const __half2*)&lo[k];
            const __half2* h1 = (const __half2*)&hi[k];
            float a = 0.f;
            #pragma unroll
            for (int d2 = 0; d2 < 4; d2++) {
                float2 f0 = __half22float2(h0[d2]);
                a = fmaf(f0.x, vs[2*d2],     a);
                a = fmaf(f0.y, vs[2*d2 + 1], a);
                float2 f1 = __half22float2(h1[d2]);
                a = fmaf(f1.x, vs[8 + 2*d2], a);
                a = fmaf(f1.y, vs[9 + 2*d2], a);
            }
            ev[k] = __expf(a);
            se[buf][k][j][lane] = ev[k];
        }
        __syncthreads();
        // ---- phase B: normalize + accumulate from registers ----
        #pragma unroll
        for (int k = 0; k < IB; k++) {
            float sum = 0.f;
            #pragma unroll
            for (int jj = 0; jj < JN; jj++) sum += se[buf][k][jj][lane];
            float c = __fdividef(ev[k], sum);
            const __half2* h0 = (const __half2*)&lo[k];
            const __half2* h1 = (const __half2*)&hi[k];
            #pragma unroll
            for (int d2 = 0; d2 < 4; d2++) {
                float2 f0 = __half22float2(h0[d2]);
                s[2*d2]     = fmaf(f0.x, c, s[2*d2]);
                s[2*d2 + 1] = fmaf(f0.y, c, s[2*d2 + 1]);
                float2 f1 = __half22float2(h1[d2]);
                s[8 + 2*d2] = fmaf(f1.x, c, s[8 + 2*d2]);
                s[9 + 2*d2] = fmaf(f1.y, c, s[9 + 2*d2]);
            }
        }
        buf ^= 1;
    }

    // ---- write per-CTA partial (coalesced float4 stores) ----
    float* dst = g_part + (size_t)blockIdx.x * BJD + (size_t)b * JD + j * DN;
    #pragma unroll
    for (int q = 0; q < 4; q++)
        ((float4*)dst)[q] = make_float4(s[4*q], s[4*q+1], s[4*q+2], s[4*q+3]);
}

// -------- k_reduce: s1 = sum of partials --------------------------------
__global__ void k_reduce() {
    const int idx = blockIdx.x * 256 + threadIdx.x;   // < BJD
    float s = 0.f;
    #pragma unroll 4
    for (int p = 0; p < NP; p++) s += g_part[(size_t)p * BJD + idx];
    g_acc[BJD + idx] = s;
}

// -------- k_final: out = squash(sum of partials) -------------------------
__global__ __launch_bounds__(1024) void k_final(float* __restrict__ out) {
    const int idx = blockIdx.x * 1024 + threadIdx.x;   // b*160 + jd
    float v = 0.f;
    #pragma unroll 4
    for (int p = 0; p < NP; p++) v += g_part[(size_t)p * BJD + idx];
    float sq = v * v;
    sq += __shfl_xor_sync(0xffffffff, sq, 1);
    sq += __shfl_xor_sync(0xffffffff, sq, 2);
    sq += __shfl_xor_sync(0xffffffff, sq, 4);
    sq += __shfl_xor_sync(0xffffffff, sq, 8);
    float sc = (sq / (1.0f + sq)) * rsqrtf(sq + 1e-7f);
    out[idx] = v * sc;
}

// -------- launch --------------------------------------------------------
extern "C" void kernel_launch(void* const* d_in, const int* in_sizes, int n_in,
                              void* d_out, int out_size) {
    const float* x = (const float*)d_in[0];   // [256,1152,8]
    const float* W = (const float*)d_in[1];   // [10,1152,16,8]
    float* out = (float*)d_out;               // [256,10,16]

    void* acc_ptr = nullptr;
    cudaGetSymbolAddress(&acc_ptr, g_acc);
    cudaMemsetAsync(acc_ptr, 0, BJD * sizeof(float));   // s0 only

    k_uhat<<<dim3(ICAPS / 16, BATCH / 64), 320>>>(x, W);
    k_pass<<<dim3(NP, BATCH / BT), dim3(BT, JN)>>>(1);
    k_reduce<<<BJD / 256, 256>>>();
    k_pass<<<dim3(NP, BATCH / BT), dim3(BT, JN)>>>(2);
    k_final<<<BJD / 1024, 1024>>>(out);
}